// round 14
// baseline (speedup 1.0000x reference)
#include <cuda_runtime.h>
#include <cuda_bf16.h>
#include <cstdint>
#include <math.h>

// Problem constants
#define NN    4096
#define NFEAT 64
#define NHID  64
#define NCLS  32
#define NG    3
#define NR    2
#define KSPL  3                  // K-split per role (chunks {86,85,85})
#define NPART (NR * KSPL)        // 6 partials per gene

// adj is fed to tf32 mma as raw fp32 bits (HW truncation). For adj>=0 with
// uniform mantissa tail this shrinks results by mean (1 - 2^-12); compensate:
#define CORR 1.000244140625f

// ---------------- device scratch (static, no allocation) ----------------
__device__ float g_s1[NG * NR * NN * NHID];      // S1 row-major, tf32-rounded
__device__ float g_hp1[NG * NPART * NN * NHID];  // partials (18.9 MB)
__device__ float g_h1[NG * NN * NHID];
__device__ float g_s2[NG * NR * NN * NCLS];
__device__ float g_hp2[NG * NPART * NN * NCLS];
__device__ float g_h2[NG * NN * NCLS];
__device__ float g_p1[NG * 64];
__device__ float g_p2[NG * 64];
__device__ float g_a1[NG];
__device__ float g_a2[NG];
__device__ int   g_cnt1;
__device__ int   g_cnt2;
__device__ int   g_flag2;
__device__ int   g_done2;

// ---------------- helpers ----------------
__device__ __forceinline__ unsigned f2tf(float x) {
    unsigned r;
    asm("cvt.rna.tf32.f32 %0, %1;" : "=r"(r) : "f"(x));
    return r;
}

__device__ __forceinline__ void mma_tf32(float* d, const unsigned* a, const unsigned* b) {
    asm volatile(
        "mma.sync.aligned.m16n8k8.row.col.f32.tf32.tf32.f32 "
        "{%0,%1,%2,%3}, {%4,%5,%6,%7}, {%8,%9}, {%0,%1,%2,%3};"
        : "+f"(d[0]), "+f"(d[1]), "+f"(d[2]), "+f"(d[3])
        : "r"(a[0]), "r"(a[1]), "r"(a[2]), "r"(a[3]), "r"(b[0]), "r"(b[1]));
}

__device__ __forceinline__ void cp16(uint32_t smem_dst, const void* gsrc) {
    asm volatile("cp.async.cg.shared.global [%0], [%1], 16;" :: "r"(smem_dst), "l"(gsrc));
}
#define CP_COMMIT() asm volatile("cp.async.commit_group;")

__device__ __forceinline__ uint32_t su32(const void* p) {
    return (uint32_t)__cvta_generic_to_shared(p);
}

// A-tile SW128 packing: two 64B m-rows per 128B line, seg XOR (line&7).
__device__ __forceinline__ uint32_t swzA(int r, int c) {
    uint32_t seg = (uint32_t)(((r & 1) << 2) | (c >> 2));
    return (uint32_t)((r >> 1) * 128) + ((seg ^ ((r >> 1) & 7)) << 4) + ((c & 3) << 2);
}

// ---------------- small fp32 GEMM: OUT[gr] = tf32(IN @ W[gr]) row-major ----------------
template <int NOUT>
__global__ void __launch_bounds__(256) small_gemm(const float* __restrict__ IN,
                                                  const float* __restrict__ W,
                                                  float* __restrict__ OUT) {
    __shared__ float Xs[64][65];
    __shared__ float Ws[64][NOUT + 1];
    const int tid  = threadIdx.x;
    const int row0 = blockIdx.x * 64;
    const int gr   = blockIdx.y;

#pragma unroll
    for (int it = 0; it < 16; ++it) {
        int idx = tid + it * 256;
        Xs[idx >> 6][idx & 63] = IN[(size_t)(row0 + (idx >> 6)) * 64 + (idx & 63)];
    }
    const float* Wg = W + (size_t)gr * 64 * NOUT;
#pragma unroll
    for (int it = 0; it < (64 * NOUT) / 256; ++it) {
        int idx = tid + it * 256;
        Ws[idx / NOUT][idx % NOUT] = Wg[idx];
    }
    __syncthreads();

    constexpr int TX  = NOUT / 4;
    constexpr int TY  = 256 / TX;
    constexpr int RPT = 64 / TY;
    const int tx = tid % TX, ty = tid / TX;
    const int c0 = tx * 4, r0 = ty * RPT;

    float acc[RPT][4];
#pragma unroll
    for (int i = 0; i < RPT; ++i)
#pragma unroll
        for (int j = 0; j < 4; ++j) acc[i][j] = 0.f;

#pragma unroll
    for (int k = 0; k < 64; ++k) {
        float bb[4];
#pragma unroll
        for (int j = 0; j < 4; ++j) bb[j] = Ws[k][c0 + j];
#pragma unroll
        for (int i = 0; i < RPT; ++i) {
            float av = Xs[r0 + i][k];
#pragma unroll
            for (int j = 0; j < 4; ++j) acc[i][j] = fmaf(av, bb[j], acc[i][j]);
        }
    }
    float* Og = OUT + ((size_t)gr * NN + row0) * NOUT;
#pragma unroll
    for (int i = 0; i < RPT; ++i)
#pragma unroll
        for (int j = 0; j < 4; ++j)
            Og[(size_t)(r0 + i) * NOUT + c0 + j] = __uint_as_float(f2tf(acc[i][j]));
}

// ---------------- combine + layer-2 projection (row-major) ----------------
__global__ void __launch_bounds__(256) combine_gemm(const float* __restrict__ H,
                                                    const float* __restrict__ a,
                                                    const float* __restrict__ W,
                                                    float* __restrict__ OUT) {
    constexpr int NOUT = NCLS;
    __shared__ float Xs[64][65];
    __shared__ float Ws[64][NOUT + 1];
    const int tid  = threadIdx.x;
    const int row0 = blockIdx.x * 64;
    const int gr   = blockIdx.y;
    const float a0 = a[0], a1v = a[1], a2v = a[2];

    const size_t gstride = (size_t)NN * NHID;
#pragma unroll
    for (int it = 0; it < 16; ++it) {
        int idx = tid + it * 256;
        int r = idx >> 6, c = idx & 63;
        size_t off = (size_t)(row0 + r) * NHID + c;
        Xs[r][c] = a0 * H[off] + a1v * H[off + gstride] + a2v * H[off + 2 * gstride];
    }
    const float* Wg = W + (size_t)gr * 64 * NOUT;
#pragma unroll
    for (int it = 0; it < (64 * NOUT) / 256; ++it) {
        int idx = tid + it * 256;
        Ws[idx / NOUT][idx % NOUT] = Wg[idx];
    }
    __syncthreads();

    constexpr int TX  = NOUT / 4;   // 8
    constexpr int TY  = 256 / TX;   // 32
    constexpr int RPT = 64 / TY;    // 2
    const int tx = tid % TX, ty = tid / TX;
    const int c0 = tx * 4, r0 = ty * RPT;

    float acc[RPT][4];
#pragma unroll
    for (int i = 0; i < RPT; ++i)
#pragma unroll
        for (int j = 0; j < 4; ++j) acc[i][j] = 0.f;

#pragma unroll
    for (int k = 0; k < 64; ++k) {
        float bb[4];
#pragma unroll
        for (int j = 0; j < 4; ++j) bb[j] = Ws[k][c0 + j];
#pragma unroll
        for (int i = 0; i < RPT; ++i) {
            float av = Xs[r0 + i][k];
#pragma unroll
            for (int j = 0; j < 4; ++j) acc[i][j] = fmaf(av, bb[j], acc[i][j]);
        }
    }
    float* Og = OUT + ((size_t)gr * NN + row0) * NOUT;
#pragma unroll
    for (int i = 0; i < RPT; ++i)
#pragma unroll
        for (int j = 0; j < 4; ++j)
            Og[(size_t)(r0 + i) * NOUT + c0 + j] = __uint_as_float(f2tf(acc[i][j]));
}

// ---------------- big GEMM: Hp[g, role*KSPL+ks] = adj[g,role][:, kslice] @ S[g,role][kslice,:] ----
// grid (32, 3, 6), 256 threads (8 warps). TM=128, KB=16, ST=4, lookahead 2.
// A stage SW128-packed (8 KB, conflict-free). R10-proven inner loop — FROZEN.
template <int NOUT>
__global__ void __launch_bounds__(256) big_gemm5(const float* __restrict__ adj,
                                                 const float* __restrict__ S,
                                                 float* __restrict__ Hp) {
    constexpr int TM   = 128;
    constexpr int KB   = 16;
    constexpr int ST   = 4;
    constexpr int ASZB = TM * 64;                     // 8192 bytes per A stage
    constexpr int BPAD = NOUT + 8;
    constexpr int BSZB = KB * BPAD * 4;               // bytes per B stage
    constexpr int WN   = (NOUT == 64) ? 32 : 16;
    constexpr int NJ   = WN / 8;                      // 4 or 2
    constexpr int MI   = 2;                           // WM = 32
    constexpr int SEGS = NOUT / 4;
    constexpr int BTOT = KB * SEGS;                   // B 16B-segs per chunk

    extern __shared__ char dyn[];
    char* Abuf = dyn;
    char* Bbuf = dyn + ST * ASZB;

    const int g    = blockIdx.y;
    const int zi   = blockIdx.z;                      // role*KSPL + ks
    const int role = zi / KSPL;
    const int ks   = zi % KSPL;
    const int row0 = blockIdx.x * TM;
    const int tid  = threadIdx.x;
    const int warp = tid >> 5, lane = tid & 31;
    const int gid  = lane >> 2, tg = lane & 3;
    const int wm   = warp >> 1, wn = warp & 1;        // 4x2 warp grid
    const int wrow = wm * 32, wcol = wn * WN;

    // uneven K split over 256 chunks: {86, 85, 85}
    const int c0   = (ks == 0) ? 0 : (86 + 85 * (ks - 1));
    const int cend = (ks == 0) ? 86 : (c0 + 85);

    float acc[MI][NJ][4];
#pragma unroll
    for (int i = 0; i < MI; ++i)
#pragma unroll
        for (int j = 0; j < NJ; ++j)
#pragma unroll
            for (int q = 0; q < 4; ++q) acc[i][j][q] = 0.f;

    const float* Ag = adj + ((size_t)(g * NR + role) * NN + row0) * NN;
    const float* Sg = S + (size_t)(g * NR + role) * NN * NOUT;

    const uint32_t sA = su32(Abuf);
    const uint32_t sB = su32(Bbuf);

    auto load_chunk = [&](int c, int st) {
        const uint32_t As = sA + st * ASZB;
        const uint32_t Bs = sB + st * BSZB;
#pragma unroll
        for (int it = 0; it < 2; ++it) {
            int cid = tid + it * 256;
            int r = cid >> 2, s4 = cid & 3;
            uint32_t seg = (uint32_t)(((r & 1) << 2) | s4);
            uint32_t dst = (uint32_t)((r >> 1) * 128) + ((seg ^ ((r >> 1) & 7)) << 4);
            cp16(As + dst, Ag + (size_t)r * NN + c * KB + s4 * 4);
        }
#pragma unroll
        for (int it = 0; it < (BTOT + 255) / 256; ++it) {
            int cid = tid + it * 256;
            if (cid < BTOT) {
                int r = cid / SEGS, sg = cid % SEGS;
                cp16(Bs + r * (BPAD * 4) + sg * 16, Sg + (size_t)(c * KB + r) * NOUT + sg * 4);
            }
        }
    };

    // prologue: lookahead 2
    load_chunk(c0, 0); CP_COMMIT();
    load_chunk(c0 + 1, 1); CP_COMMIT();

    for (int i = c0, li = 0; i < cend; ++i, ++li) {
        const int j = i + 2;
        if (j < cend) load_chunk(j, (li + 2) & (ST - 1));
        CP_COMMIT();                                  // possibly empty group
        asm volatile("cp.async.wait_group 2;");       // chunk i resident
        __syncthreads();                              // single barrier per chunk

        const char* As = Abuf + (li & (ST - 1)) * ASZB;
        const float* Bs = (const float*)(Bbuf + (li & (ST - 1)) * BSZB);

        // preload ALL fragments for the chunk, then issue all MMAs
        unsigned afr[2][MI][4];
        unsigned bfr[2][NJ][2];
#pragma unroll
        for (int kk = 0; kk < 2; ++kk) {
            const int k0 = kk * 8;
#pragma unroll
            for (int i2 = 0; i2 < MI; ++i2) {
                const int rb = wrow + i2 * 16;
                afr[kk][i2][0] = *(const unsigned*)(As + swzA(rb + gid, k0 + tg));
                afr[kk][i2][1] = *(const unsigned*)(As + swzA(rb + gid + 8, k0 + tg));
                afr[kk][i2][2] = *(const unsigned*)(As + swzA(rb + gid, k0 + tg + 4));
                afr[kk][i2][3] = *(const unsigned*)(As + swzA(rb + gid + 8, k0 + tg + 4));
            }
#pragma unroll
            for (int j2 = 0; j2 < NJ; ++j2) {
                const int cb = wcol + j2 * 8 + gid;
                bfr[kk][j2][0] = __float_as_uint(Bs[(k0 + tg) * BPAD + cb]);
                bfr[kk][j2][1] = __float_as_uint(Bs[(k0 + tg + 4) * BPAD + cb]);
            }
        }
#pragma unroll
        for (int kk = 0; kk < 2; ++kk)
#pragma unroll
            for (int i2 = 0; i2 < MI; ++i2)
#pragma unroll
                for (int j2 = 0; j2 < NJ; ++j2)
                    mma_tf32(acc[i2][j2], afr[kk][i2], bfr[kk][j2]);
    }

    // store partials row-major
    float* Hg = Hp + ((size_t)(g * NPART + zi) * NN + row0) * NOUT;
#pragma unroll
    for (int i2 = 0; i2 < MI; ++i2) {
#pragma unroll
        for (int j2 = 0; j2 < NJ; ++j2) {
            const int r0 = wrow + i2 * 16 + gid;
            const int cc = wcol + j2 * 8 + tg * 2;
            *(float2*)&Hg[(size_t)r0 * NOUT + cc]       = make_float2(acc[i2][j2][0], acc[i2][j2][1]);
            *(float2*)&Hg[(size_t)(r0 + 8) * NOUT + cc] = make_float2(acc[i2][j2][2], acc[i2][j2][3]);
        }
    }
}

// ---------------- fuse + attention (+ optional fused final combine) ----------------
// H[g] = relu(CORR*sum_p Hp[g,p] + b[g]); last CTA computes softmax weights a.
// If DO_COMBINE: after a is published (flag), gene-0 CTAs combine out = sum_g a[g]*H[g].
// Safe soft grid-sync: all 192 CTAs are co-resident (grid < #SMs, tiny smem/regs).
template <int NOUT, bool DO_COMBINE>
__global__ void __launch_bounds__(256) fuse_attn(const float* __restrict__ Hp,
                                                 const float* __restrict__ bias,
                                                 const float* __restrict__ Wk,
                                                 const float* __restrict__ Wq,
                                                 int layer, float inv_cnt,
                                                 float* __restrict__ H,
                                                 float* __restrict__ parts,
                                                 float* __restrict__ a_out,
                                                 int* __restrict__ cnt,
                                                 float* __restrict__ out,
                                                 int* __restrict__ flag,
                                                 int* __restrict__ done) {
    constexpr int Q4G = NN * NOUT / 4;
    constexpr int EPT = Q4G / (64 * 256);
    constexpr int CG  = NOUT / 4;
    const int g   = blockIdx.y;
    const int tid = threadIdx.x;

    const float4* base = (const float4*)(Hp + (size_t)g * NPART * NN * NOUT);
    float4* Hg = (float4*)(H + (size_t)g * NN * NOUT);
    const float4* bv = (const float4*)(bias + g * NOUT);

    float lsum = 0.f;
#pragma unroll
    for (int it = 0; it < EPT; ++it) {
        int idx = blockIdx.x * 256 + tid + it * (64 * 256);
        float4 acc = base[idx];
#pragma unroll
        for (int p = 1; p < NPART; ++p) {
            float4 v = base[(size_t)p * Q4G + idx];
            acc.x += v.x; acc.y += v.y; acc.z += v.z; acc.w += v.w;
        }
        float4 bb = bv[idx % CG];
        float4 r;
        r.x = fmaxf(CORR * acc.x + bb.x, 0.f);
        r.y = fmaxf(CORR * acc.y + bb.y, 0.f);
        r.z = fmaxf(CORR * acc.z + bb.z, 0.f);
        r.w = fmaxf(CORR * acc.w + bb.w, 0.f);
        Hg[idx] = r;
        lsum += r.x + r.y + r.z + r.w;
    }
#pragma unroll
    for (int off = 16; off; off >>= 1) lsum += __shfl_xor_sync(0xffffffffu, lsum, off);
    __shared__ float wsum[8];
    if ((tid & 31) == 0) wsum[tid >> 5] = lsum;
    __syncthreads();
    if (tid == 0) {
        float s = 0.f;
#pragma unroll
        for (int w = 0; w < 8; ++w) s += wsum[w];
        parts[g * 64 + blockIdx.x] = s;
    }

    __threadfence();
    __shared__ int lastb;
    if (tid == 0) lastb = (atomicAdd(cnt, 1) == 64 * NG - 1) ? 1 : 0;
    __syncthreads();

    if (lastb) {
        __shared__ float ssq[NG];
        if (tid < NG) {
            float s = 0.f;
            for (int i = 0; i < 64; ++i) s += parts[tid * 64 + i];   // fixed order
            ssq[tid] = s * inv_cnt;
        }
        __syncthreads();
        if (tid == 0) {
            const float* wk = Wk + layer * 9;
            const float* wq = Wq + layer * 9;
            float kk[NG], lg[NG];
#pragma unroll
            for (int j = 0; j < NG; ++j)
                kk[j] = fmaxf(ssq[0] * wk[j] + ssq[1] * wk[3 + j] + ssq[2] * wk[6 + j], 0.f);
            float m = -1e30f;
#pragma unroll
            for (int j = 0; j < NG; ++j) {
                lg[j] = kk[0] * wq[j] + kk[1] * wq[3 + j] + kk[2] * wq[6 + j];
                m = fmaxf(m, lg[j]);
            }
            float e0 = expf(lg[0] - m), e1 = expf(lg[1] - m), e2 = expf(lg[2] - m);
            float inv = 1.f / (e0 + e1 + e2);
            a_out[0] = e0 * inv;
            a_out[1] = e1 * inv;
            a_out[2] = e2 * inv;
            *cnt = 0;   // reset for replay
            if (DO_COMBINE) {
                __threadfence();
                atomicExch(flag, 1);    // publish a_out + all H (fenced above)
            }
        }
    }

    if (DO_COMBINE) {
        if (g != 0) return;             // only gene-0 CTAs combine (all co-resident)
        if (tid == 0) {
            while (atomicAdd(flag, 0) == 0) {}
        }
        __syncthreads();
        // L1-bypass loads: a_out and other genes' H were written by other CTAs
        const float a0 = __ldcg(&a_out[0]);
        const float a1 = __ldcg(&a_out[1]);
        const float a2 = __ldcg(&a_out[2]);
        constexpr int Q = NN * NOUT / 4;           // total float4 in one gene
        constexpr int PER = Q / 64;                // per combiner CTA
        const float4* h4 = (const float4*)H;
        float4* o4 = (float4*)out;
        for (int it = 0; it < PER / 256; ++it) {
            int idx = blockIdx.x * PER + tid + it * 256;
            float4 x0 = __ldcg(&h4[idx]);
            float4 x1 = __ldcg(&h4[idx + Q]);
            float4 x2 = __ldcg(&h4[idx + 2 * Q]);
            float4 r;
            r.x = a0 * x0.x + a1 * x1.x + a2 * x2.x;
            r.y = a0 * x0.y + a1 * x1.y + a2 * x2.y;
            r.z = a0 * x0.z + a1 * x1.z + a2 * x2.z;
            r.w = a0 * x0.w + a1 * x1.w + a2 * x2.w;
            o4[idx] = r;
        }
        __threadfence();
        if (tid == 0) {
            // last finisher resets; every combiner has passed the spin by then
            if (atomicAdd(done, 1) == 63) {
                atomicExch(done, 0);
                atomicExch(flag, 0);
            }
        }
    }
}

// ---------------- launch ----------------
extern "C" void kernel_launch(void* const* d_in, const int* in_sizes, int n_in,
                              void* d_out, int out_size) {
    const float* x   = (const float*)d_in[0];
    const float* adj = (const float*)d_in[1];
    const float* W1  = (const float*)d_in[2];
    const float* b1  = (const float*)d_in[3];
    const float* W2  = (const float*)d_in[4];
    const float* b2  = (const float*)d_in[5];
    const float* Wk  = (const float*)d_in[6];
    const float* Wq  = (const float*)d_in[7];
    float* out = (float*)d_out;

    float *s1, *hp1, *h1, *s2, *hp2, *h2, *p1, *p2, *a1, *a2;
    int *c1, *c2, *fl2, *dn2;
    cudaGetSymbolAddress((void**)&s1, g_s1);
    cudaGetSymbolAddress((void**)&hp1, g_hp1);
    cudaGetSymbolAddress((void**)&h1, g_h1);
    cudaGetSymbolAddress((void**)&s2, g_s2);
    cudaGetSymbolAddress((void**)&hp2, g_hp2);
    cudaGetSymbolAddress((void**)&h2, g_h2);
    cudaGetSymbolAddress((void**)&p1, g_p1);
    cudaGetSymbolAddress((void**)&p2, g_p2);
    cudaGetSymbolAddress((void**)&a1, g_a1);
    cudaGetSymbolAddress((void**)&a2, g_a2);
    cudaGetSymbolAddress((void**)&c1, g_cnt1);
    cudaGetSymbolAddress((void**)&c2, g_cnt2);
    cudaGetSymbolAddress((void**)&fl2, g_flag2);
    cudaGetSymbolAddress((void**)&dn2, g_done2);

    constexpr int SM64 = 4 * (128 * 64 + 16 * (NHID + 8) * 4);   // 51200 B
    constexpr int SM32 = 4 * (128 * 64 + 16 * (NCLS + 8) * 4);   // 43008 B
    cudaFuncSetAttribute(big_gemm5<NHID>, cudaFuncAttributeMaxDynamicSharedMemorySize, SM64);
    cudaFuncSetAttribute(big_gemm5<NCLS>, cudaFuncAttributeMaxDynamicSharedMemorySize, SM32);

    // Layer 1
    small_gemm<NHID><<<dim3(NN / 64, NG * NR), 256>>>(x, W1, s1);
    big_gemm5<NHID><<<dim3(NN / 128, NG, NPART), 256, SM64>>>(adj, s1, hp1);
    fuse_attn<NHID, false><<<dim3(64, NG), 256>>>(hp1, b1, Wk, Wq, 0,
                                                  1.f / ((float)NN * NHID),
                                                  h1, p1, a1, c1,
                                                  nullptr, nullptr, nullptr);
    // Layer 2 (combine fused into projection; final combine fused into fuse_attn)
    combine_gemm<<<dim3(NN / 64, NG * NR), 256>>>(h1, a1, W2, s2);
    big_gemm5<NCLS><<<dim3(NN / 128, NG, NPART), 256, SM32>>>(adj, s2, hp2);
    fuse_attn<NCLS, true><<<dim3(64, NG), 256>>>(hp2, b2, Wk, Wq, 1,
                                                 1.f / ((float)NN * NCLS),
                                                 h2, p2, a2, c2,
                                                 out, fl2, dn2);
}

// round 15
// speedup vs baseline: 1.0083x; 1.0083x over previous
#include <cuda_runtime.h>
#include <cuda_bf16.h>
#include <cstdint>
#include <math.h>

// Problem constants
#define NN    4096
#define NFEAT 64
#define NHID  64
#define NCLS  32
#define NG    3
#define NR    2
#define KSPL  3                  // K-split per role (chunks {86,85,85})
#define NPART (NR * KSPL)        // 6 partials per gene

// adj is fed to tf32 mma as raw fp32 bits (HW truncation). For adj>=0 with
// uniform mantissa tail this shrinks results by mean (1 - 2^-12); compensate:
#define CORR 1.000244140625f

// ---------------- device scratch (static, no allocation) ----------------
__device__ float g_s1[NG * NR * NN * NHID];      // S1 row-major, tf32-rounded
__device__ float g_hp1[NG * NPART * NN * NHID];  // partials (18.9 MB)
__device__ float g_h1[NG * NN * NHID];
__device__ float g_s2[NG * NR * NN * NCLS];
__device__ float g_hp2[NG * NPART * NN * NCLS];
__device__ float g_h2[NG * NN * NCLS];
__device__ float g_p1[NG * 64];
__device__ float g_p2[NG * 64];
__device__ float g_a1[NG];
__device__ float g_a2[NG];
__device__ int   g_cnt1;
__device__ int   g_cnt2;
__device__ int   g_flag2;
__device__ int   g_done2;

// ---------------- helpers ----------------
__device__ __forceinline__ unsigned f2tf(float x) {
    unsigned r;
    asm("cvt.rna.tf32.f32 %0, %1;" : "=r"(r) : "f"(x));
    return r;
}

__device__ __forceinline__ void mma_tf32(float* d, const unsigned* a, const unsigned* b) {
    asm volatile(
        "mma.sync.aligned.m16n8k8.row.col.f32.tf32.tf32.f32 "
        "{%0,%1,%2,%3}, {%4,%5,%6,%7}, {%8,%9}, {%0,%1,%2,%3};"
        : "+f"(d[0]), "+f"(d[1]), "+f"(d[2]), "+f"(d[3])
        : "r"(a[0]), "r"(a[1]), "r"(a[2]), "r"(a[3]), "r"(b[0]), "r"(b[1]));
}

__device__ __forceinline__ void cp16(uint32_t smem_dst, const void* gsrc) {
    asm volatile("cp.async.cg.shared.global [%0], [%1], 16;" :: "r"(smem_dst), "l"(gsrc));
}
#define CP_COMMIT() asm volatile("cp.async.commit_group;")

__device__ __forceinline__ uint32_t su32(const void* p) {
    return (uint32_t)__cvta_generic_to_shared(p);
}

// A-tile SW128 packing: two 64B m-rows per 128B line, seg XOR (line&7).
__device__ __forceinline__ uint32_t swzA(int r, int c) {
    uint32_t seg = (uint32_t)(((r & 1) << 2) | (c >> 2));
    return (uint32_t)((r >> 1) * 128) + ((seg ^ ((r >> 1) & 7)) << 4) + ((c & 3) << 2);
}

// ldmatrix x4 (b16 form carrying tf32): matrices 0..3 = a0..a3 of m16n8k8 frag.
__device__ __forceinline__ void ldsm_x4(unsigned* a, uint32_t addr) {
    asm volatile("ldmatrix.sync.aligned.m8n8.x4.shared.b16 {%0,%1,%2,%3}, [%4];"
                 : "=r"(a[0]), "=r"(a[1]), "=r"(a[2]), "=r"(a[3])
                 : "r"(addr));
}

// ---------------- small fp32 GEMM: OUT[gr] = tf32(IN @ W[gr]) row-major ----------------
template <int NOUT>
__global__ void __launch_bounds__(256) small_gemm(const float* __restrict__ IN,
                                                  const float* __restrict__ W,
                                                  float* __restrict__ OUT) {
    __shared__ float Xs[64][65];
    __shared__ float Ws[64][NOUT + 1];
    const int tid  = threadIdx.x;
    const int row0 = blockIdx.x * 64;
    const int gr   = blockIdx.y;

#pragma unroll
    for (int it = 0; it < 16; ++it) {
        int idx = tid + it * 256;
        Xs[idx >> 6][idx & 63] = IN[(size_t)(row0 + (idx >> 6)) * 64 + (idx & 63)];
    }
    const float* Wg = W + (size_t)gr * 64 * NOUT;
#pragma unroll
    for (int it = 0; it < (64 * NOUT) / 256; ++it) {
        int idx = tid + it * 256;
        Ws[idx / NOUT][idx % NOUT] = Wg[idx];
    }
    __syncthreads();

    constexpr int TX  = NOUT / 4;
    constexpr int TY  = 256 / TX;
    constexpr int RPT = 64 / TY;
    const int tx = tid % TX, ty = tid / TX;
    const int c0 = tx * 4, r0 = ty * RPT;

    float acc[RPT][4];
#pragma unroll
    for (int i = 0; i < RPT; ++i)
#pragma unroll
        for (int j = 0; j < 4; ++j) acc[i][j] = 0.f;

#pragma unroll
    for (int k = 0; k < 64; ++k) {
        float bb[4];
#pragma unroll
        for (int j = 0; j < 4; ++j) bb[j] = Ws[k][c0 + j];
#pragma unroll
        for (int i = 0; i < RPT; ++i) {
            float av = Xs[r0 + i][k];
#pragma unroll
            for (int j = 0; j < 4; ++j) acc[i][j] = fmaf(av, bb[j], acc[i][j]);
        }
    }
    float* Og = OUT + ((size_t)gr * NN + row0) * NOUT;
#pragma unroll
    for (int i = 0; i < RPT; ++i)
#pragma unroll
        for (int j = 0; j < 4; ++j)
            Og[(size_t)(r0 + i) * NOUT + c0 + j] = __uint_as_float(f2tf(acc[i][j]));
}

// ---------------- combine + layer-2 projection (row-major) ----------------
__global__ void __launch_bounds__(256) combine_gemm(const float* __restrict__ H,
                                                    const float* __restrict__ a,
                                                    const float* __restrict__ W,
                                                    float* __restrict__ OUT) {
    constexpr int NOUT = NCLS;
    __shared__ float Xs[64][65];
    __shared__ float Ws[64][NOUT + 1];
    const int tid  = threadIdx.x;
    const int row0 = blockIdx.x * 64;
    const int gr   = blockIdx.y;
    const float a0 = a[0], a1v = a[1], a2v = a[2];

    const size_t gstride = (size_t)NN * NHID;
#pragma unroll
    for (int it = 0; it < 16; ++it) {
        int idx = tid + it * 256;
        int r = idx >> 6, c = idx & 63;
        size_t off = (size_t)(row0 + r) * NHID + c;
        Xs[r][c] = a0 * H[off] + a1v * H[off + gstride] + a2v * H[off + 2 * gstride];
    }
    const float* Wg = W + (size_t)gr * 64 * NOUT;
#pragma unroll
    for (int it = 0; it < (64 * NOUT) / 256; ++it) {
        int idx = tid + it * 256;
        Ws[idx / NOUT][idx % NOUT] = Wg[idx];
    }
    __syncthreads();

    constexpr int TX  = NOUT / 4;   // 8
    constexpr int TY  = 256 / TX;   // 32
    constexpr int RPT = 64 / TY;    // 2
    const int tx = tid % TX, ty = tid / TX;
    const int c0 = tx * 4, r0 = ty * RPT;

    float acc[RPT][4];
#pragma unroll
    for (int i = 0; i < RPT; ++i)
#pragma unroll
        for (int j = 0; j < 4; ++j) acc[i][j] = 0.f;

#pragma unroll
    for (int k = 0; k < 64; ++k) {
        float bb[4];
#pragma unroll
        for (int j = 0; j < 4; ++j) bb[j] = Ws[k][c0 + j];
#pragma unroll
        for (int i = 0; i < RPT; ++i) {
            float av = Xs[r0 + i][k];
#pragma unroll
            for (int j = 0; j < 4; ++j) acc[i][j] = fmaf(av, bb[j], acc[i][j]);
        }
    }
    float* Og = OUT + ((size_t)gr * NN + row0) * NOUT;
#pragma unroll
    for (int i = 0; i < RPT; ++i)
#pragma unroll
        for (int j = 0; j < 4; ++j)
            Og[(size_t)(r0 + i) * NOUT + c0 + j] = __uint_as_float(f2tf(acc[i][j]));
}

// ---------------- big GEMM: Hp[g, role*KSPL+ks] = adj[g,role][:, kslice] @ S[g,role][kslice,:] ----
// grid (32, 3, 6), 256 threads (8 warps). TM=128, KB=16, ST=4, lookahead 2.
// A stage SW128-packed; A fragments via ldmatrix.x4 (4 instr/warp/chunk instead of 16 LDS).
template <int NOUT>
__global__ void __launch_bounds__(256) big_gemm8(const float* __restrict__ adj,
                                                 const float* __restrict__ S,
                                                 float* __restrict__ Hp) {
    constexpr int TM   = 128;
    constexpr int KB   = 16;
    constexpr int ST   = 4;
    constexpr int ASZB = TM * 64;                     // 8192 bytes per A stage
    constexpr int BPAD = NOUT + 8;
    constexpr int BSZB = KB * BPAD * 4;               // bytes per B stage
    constexpr int WN   = (NOUT == 64) ? 32 : 16;
    constexpr int NJ   = WN / 8;                      // 4 or 2
    constexpr int MI   = 2;                           // WM = 32
    constexpr int SEGS = NOUT / 4;
    constexpr int BTOT = KB * SEGS;                   // B 16B-segs per chunk

    extern __shared__ char dyn[];
    char* Abuf = dyn;
    char* Bbuf = dyn + ST * ASZB;

    const int g    = blockIdx.y;
    const int zi   = blockIdx.z;                      // role*KSPL + ks
    const int role = zi / KSPL;
    const int ks   = zi % KSPL;
    const int row0 = blockIdx.x * TM;
    const int tid  = threadIdx.x;
    const int warp = tid >> 5, lane = tid & 31;
    const int gid  = lane >> 2, tg = lane & 3;
    const int wm   = warp >> 1, wn = warp & 1;        // 4x2 warp grid
    const int wrow = wm * 32, wcol = wn * WN;

    // ldmatrix lane mapping: matrices 0..3 = (a0,a1,a2,a3)
    const int lrow = (lane & 7) + (lane & 8);         // row within 16-row tile
    const int lsel = (lane >> 2) & 4;                 // +4 cols for matrices 2,3

    // uneven K split over 256 chunks: {86, 85, 85}
    const int c0   = (ks == 0) ? 0 : (86 + 85 * (ks - 1));
    const int cend = (ks == 0) ? 86 : (c0 + 85);

    float acc[MI][NJ][4];
#pragma unroll
    for (int i = 0; i < MI; ++i)
#pragma unroll
        for (int j = 0; j < NJ; ++j)
#pragma unroll
            for (int q = 0; q < 4; ++q) acc[i][j][q] = 0.f;

    const float* Ag = adj + ((size_t)(g * NR + role) * NN + row0) * NN;
    const float* Sg = S + (size_t)(g * NR + role) * NN * NOUT;

    const uint32_t sA = su32(Abuf);
    const uint32_t sB = su32(Bbuf);

    auto load_chunk = [&](int c, int st) {
        const uint32_t As = sA + st * ASZB;
        const uint32_t Bs = sB + st * BSZB;
#pragma unroll
        for (int it = 0; it < 2; ++it) {
            int cid = tid + it * 256;
            int r = cid >> 2, s4 = cid & 3;
            uint32_t seg = (uint32_t)(((r & 1) << 2) | s4);
            uint32_t dst = (uint32_t)((r >> 1) * 128) + ((seg ^ ((r >> 1) & 7)) << 4);
            cp16(As + dst, Ag + (size_t)r * NN + c * KB + s4 * 4);
        }
#pragma unroll
        for (int it = 0; it < (BTOT + 255) / 256; ++it) {
            int cid = tid + it * 256;
            if (cid < BTOT) {
                int r = cid / SEGS, sg = cid % SEGS;
                cp16(Bs + r * (BPAD * 4) + sg * 16, Sg + (size_t)(c * KB + r) * NOUT + sg * 4);
            }
        }
    };

    // prologue: lookahead 2
    load_chunk(c0, 0); CP_COMMIT();
    load_chunk(c0 + 1, 1); CP_COMMIT();

    for (int i = c0, li = 0; i < cend; ++i, ++li) {
        const int j = i + 2;
        if (j < cend) load_chunk(j, (li + 2) & (ST - 1));
        CP_COMMIT();                                  // possibly empty group
        asm volatile("cp.async.wait_group 2;");       // chunk i resident
        __syncthreads();                              // single barrier per chunk

        const uint32_t AsU = sA + (li & (ST - 1)) * ASZB;
        const float* Bs = (const float*)(Bbuf + (li & (ST - 1)) * BSZB);

        // preload ALL fragments for the chunk (A via ldmatrix), then issue all MMAs
        unsigned afr[2][MI][4];
        unsigned bfr[2][NJ][2];
#pragma unroll
        for (int kk = 0; kk < 2; ++kk) {
            const int k0 = kk * 8;
#pragma unroll
            for (int i2 = 0; i2 < MI; ++i2)
                ldsm_x4(afr[kk][i2], AsU + swzA(wrow + i2 * 16 + lrow, k0 + lsel));
#pragma unroll
            for (int j2 = 0; j2 < NJ; ++j2) {
                const int cb = wcol + j2 * 8 + gid;
                bfr[kk][j2][0] = __float_as_uint(Bs[(k0 + tg) * BPAD + cb]);
                bfr[kk][j2][1] = __float_as_uint(Bs[(k0 + tg + 4) * BPAD + cb]);
            }
        }
#pragma unroll
        for (int kk = 0; kk < 2; ++kk)
#pragma unroll
            for (int i2 = 0; i2 < MI; ++i2)
#pragma unroll
                for (int j2 = 0; j2 < NJ; ++j2)
                    mma_tf32(acc[i2][j2], afr[kk][i2], bfr[kk][j2]);
    }

    // store partials row-major
    float* Hg = Hp + ((size_t)(g * NPART + zi) * NN + row0) * NOUT;
#pragma unroll
    for (int i2 = 0; i2 < MI; ++i2) {
#pragma unroll
        for (int j2 = 0; j2 < NJ; ++j2) {
            const int r0 = wrow + i2 * 16 + gid;
            const int cc = wcol + j2 * 8 + tg * 2;
            *(float2*)&Hg[(size_t)r0 * NOUT + cc]       = make_float2(acc[i2][j2][0], acc[i2][j2][1]);
            *(float2*)&Hg[(size_t)(r0 + 8) * NOUT + cc] = make_float2(acc[i2][j2][2], acc[i2][j2][3]);
        }
    }
}

// ---------------- fuse + attention (+ optional fused final combine) ----------------
template <int NOUT, bool DO_COMBINE>
__global__ void __launch_bounds__(256) fuse_attn(const float* __restrict__ Hp,
                                                 const float* __restrict__ bias,
                                                 const float* __restrict__ Wk,
                                                 const float* __restrict__ Wq,
                                                 int layer, float inv_cnt,
                                                 float* __restrict__ H,
                                                 float* __restrict__ parts,
                                                 float* __restrict__ a_out,
                                                 int* __restrict__ cnt,
                                                 float* __restrict__ out,
                                                 int* __restrict__ flag,
                                                 int* __restrict__ done) {
    constexpr int Q4G = NN * NOUT / 4;
    constexpr int EPT = Q4G / (64 * 256);
    constexpr int CG  = NOUT / 4;
    const int g   = blockIdx.y;
    const int tid = threadIdx.x;

    const float4* base = (const float4*)(Hp + (size_t)g * NPART * NN * NOUT);
    float4* Hg = (float4*)(H + (size_t)g * NN * NOUT);
    const float4* bv = (const float4*)(bias + g * NOUT);

    float lsum = 0.f;
#pragma unroll
    for (int it = 0; it < EPT; ++it) {
        int idx = blockIdx.x * 256 + tid + it * (64 * 256);
        float4 acc = base[idx];
#pragma unroll
        for (int p = 1; p < NPART; ++p) {
            float4 v = base[(size_t)p * Q4G + idx];
            acc.x += v.x; acc.y += v.y; acc.z += v.z; acc.w += v.w;
        }
        float4 bb = bv[idx % CG];
        float4 r;
        r.x = fmaxf(CORR * acc.x + bb.x, 0.f);
        r.y = fmaxf(CORR * acc.y + bb.y, 0.f);
        r.z = fmaxf(CORR * acc.z + bb.z, 0.f);
        r.w = fmaxf(CORR * acc.w + bb.w, 0.f);
        Hg[idx] = r;
        lsum += r.x + r.y + r.z + r.w;
    }
#pragma unroll
    for (int off = 16; off; off >>= 1) lsum += __shfl_xor_sync(0xffffffffu, lsum, off);
    __shared__ float wsum[8];
    if ((tid & 31) == 0) wsum[tid >> 5] = lsum;
    __syncthreads();
    if (tid == 0) {
        float s = 0.f;
#pragma unroll
        for (int w = 0; w < 8; ++w) s += wsum[w];
        parts[g * 64 + blockIdx.x] = s;
    }

    __threadfence();
    __shared__ int lastb;
    if (tid == 0) lastb = (atomicAdd(cnt, 1) == 64 * NG - 1) ? 1 : 0;
    __syncthreads();

    if (lastb) {
        __shared__ float ssq[NG];
        if (tid < NG) {
            float s = 0.f;
            for (int i = 0; i < 64; ++i) s += parts[tid * 64 + i];   // fixed order
            ssq[tid] = s * inv_cnt;
        }
        __syncthreads();
        if (tid == 0) {
            const float* wk = Wk + layer * 9;
            const float* wq = Wq + layer * 9;
            float kk[NG], lg[NG];
#pragma unroll
            for (int j = 0; j < NG; ++j)
                kk[j] = fmaxf(ssq[0] * wk[j] + ssq[1] * wk[3 + j] + ssq[2] * wk[6 + j], 0.f);
            float m = -1e30f;
#pragma unroll
            for (int j = 0; j < NG; ++j) {
                lg[j] = kk[0] * wq[j] + kk[1] * wq[3 + j] + kk[2] * wq[6 + j];
                m = fmaxf(m, lg[j]);
            }
            float e0 = expf(lg[0] - m), e1 = expf(lg[1] - m), e2 = expf(lg[2] - m);
            float inv = 1.f / (e0 + e1 + e2);
            a_out[0] = e0 * inv;
            a_out[1] = e1 * inv;
            a_out[2] = e2 * inv;
            *cnt = 0;   // reset for replay
            if (DO_COMBINE) {
                __threadfence();
                atomicExch(flag, 1);    // publish a_out + all H
            }
        }
    }

    if (DO_COMBINE) {
        if (g != 0) return;             // only gene-0 CTAs combine (all co-resident)
        if (tid == 0) {
            while (atomicAdd(flag, 0) == 0) {}
        }
        __syncthreads();
        const float a0 = __ldcg(&a_out[0]);
        const float a1 = __ldcg(&a_out[1]);
        const float a2 = __ldcg(&a_out[2]);
        constexpr int Q = NN * NOUT / 4;
        constexpr int PER = Q / 64;
        const float4* h4 = (const float4*)H;
        float4* o4 = (float4*)out;
        for (int it = 0; it < PER / 256; ++it) {
            int idx = blockIdx.x * PER + tid + it * 256;
            float4 x0 = __ldcg(&h4[idx]);
            float4 x1 = __ldcg(&h4[idx + Q]);
            float4 x2 = __ldcg(&h4[idx + 2 * Q]);
            float4 r;
            r.x = a0 * x0.x + a1 * x1.x + a2 * x2.x;
            r.y = a0 * x0.y + a1 * x1.y + a2 * x2.y;
            r.z = a0 * x0.z + a1 * x1.z + a2 * x2.z;
            r.w = a0 * x0.w + a1 * x1.w + a2 * x2.w;
            o4[idx] = r;
        }
        __threadfence();
        if (tid == 0) {
            if (atomicAdd(done, 1) == 63) {
                atomicExch(done, 0);
                atomicExch(flag, 0);
            }
        }
    }
}

// ---------------- launch ----------------
extern "C" void kernel_launch(void* const* d_in, const int* in_sizes, int n_in,
                              void* d_out, int out_size) {
    const float* x   = (const float*)d_in[0];
    const float* adj = (const float*)d_in[1];
    const float* W1  = (const float*)d_in[2];
    const float* b1  = (const float*)d_in[3];
    const float* W2  = (const float*)d_in[4];
    const float* b2  = (const float*)d_in[5];
    const float* Wk  = (const float*)d_in[6];
    const float* Wq  = (const float*)d_in[7];
    float* out = (float*)d_out;

    float *s1, *hp1, *h1, *s2, *hp2, *h2, *p1, *p2, *a1, *a2;
    int *c1, *c2, *fl2, *dn2;
    cudaGetSymbolAddress((void**)&s1, g_s1);
    cudaGetSymbolAddress((void**)&hp1, g_hp1);
    cudaGetSymbolAddress((void**)&h1, g_h1);
    cudaGetSymbolAddress((void**)&s2, g_s2);
    cudaGetSymbolAddress((void**)&hp2, g_hp2);
    cudaGetSymbolAddress((void**)&h2, g_h2);
    cudaGetSymbolAddress((void**)&p1, g_p1);
    cudaGetSymbolAddress((void**)&p2, g_p2);
    cudaGetSymbolAddress((void**)&a1, g_a1);
    cudaGetSymbolAddress((void**)&a2, g_a2);
    cudaGetSymbolAddress((void**)&c1, g_cnt1);
    cudaGetSymbolAddress((void**)&c2, g_cnt2);
    cudaGetSymbolAddress((void**)&fl2, g_flag2);
    cudaGetSymbolAddress((void**)&dn2, g_done2);

    constexpr int SM64 = 4 * (128 * 64 + 16 * (NHID + 8) * 4);   // 51200 B
    constexpr int SM32 = 4 * (128 * 64 + 16 * (NCLS + 8) * 4);   // 43008 B
    cudaFuncSetAttribute(big_gemm8<NHID>, cudaFuncAttributeMaxDynamicSharedMemorySize, SM64);
    cudaFuncSetAttribute(big_gemm8<NCLS>, cudaFuncAttributeMaxDynamicSharedMemorySize, SM32);

    // Layer 1
    small_gemm<NHID><<<dim3(NN / 64, NG * NR), 256>>>(x, W1, s1);
    big_gemm8<NHID><<<dim3(NN / 128, NG, NPART), 256, SM64>>>(adj, s1, hp1);
    fuse_attn<NHID, false><<<dim3(64, NG), 256>>>(hp1, b1, Wk, Wq, 0,
                                                  1.f / ((float)NN * NHID),
                                                  h1, p1, a1, c1,
                                                  nullptr, nullptr, nullptr);
    // Layer 2 (combine fused into projection; final combine fused into fuse_attn)
    combine_gemm<<<dim3(NN / 64, NG * NR), 256>>>(h1, a1, W2, s2);
    big_gemm8<NCLS><<<dim3(NN / 128, NG, NPART), 256, SM32>>>(adj, s2, hp2);
    fuse_attn<NCLS, true><<<dim3(64, NG), 256>>>(hp2, b2, Wk, Wq, 1,
                                                 1.f / ((float)NN * NCLS),
                                                 h2, p2, a2, c2,
                                                 out, fl2, dn2);
}

// round 17
// speedup vs baseline: 1.0153x; 1.0069x over previous
#include <cuda_runtime.h>
#include <cuda_bf16.h>
#include <cstdint>
#include <math.h>

// Problem constants
#define NN    4096
#define NFEAT 64
#define NHID  64
#define NCLS  32
#define NG    3
#define NR    2
#define KSPL  3                  // K-split per role (chunks {86,85,85})
#define NPART (NR * KSPL)        // 6 partials per gene
#define FB    128                // fuse blocks per gene

// adj is fed to tf32 mma as raw fp32 bits (HW truncation). For adj>=0 with
// uniform mantissa tail this shrinks results by mean (1 - 2^-12); compensate:
#define CORR 1.000244140625f

// ---------------- device scratch (static, no allocation) ----------------
__device__ float g_s1[NG * NR * NN * NHID];      // S1 row-major, tf32-rounded
__device__ float g_hp1[NG * NPART * NN * NHID];  // partials (18.9 MB)
__device__ float g_h1[NG * NN * NHID];
__device__ float g_s2[NG * NR * NN * NCLS];
__device__ float g_hp2[NG * NPART * NN * NCLS];
__device__ float g_h2[NG * NN * NCLS];
__device__ float g_p1[NG * FB];
__device__ float g_p2[NG * FB];
__device__ float g_a1[NG];
__device__ float g_a2[NG];
__device__ int   g_cnt1;
__device__ int   g_cnt2;
__device__ int   g_flag2;
__device__ int   g_done2;

// ---------------- helpers ----------------
__device__ __forceinline__ unsigned f2tf(float x) {
    unsigned r;
    asm("cvt.rna.tf32.f32 %0, %1;" : "=r"(r) : "f"(x));
    return r;
}

__device__ __forceinline__ void mma_tf32(float* d, const unsigned* a, const unsigned* b) {
    asm volatile(
        "mma.sync.aligned.m16n8k8.row.col.f32.tf32.tf32.f32 "
        "{%0,%1,%2,%3}, {%4,%5,%6,%7}, {%8,%9}, {%0,%1,%2,%3};"
        : "+f"(d[0]), "+f"(d[1]), "+f"(d[2]), "+f"(d[3])
        : "r"(a[0]), "r"(a[1]), "r"(a[2]), "r"(a[3]), "r"(b[0]), "r"(b[1]));
}

__device__ __forceinline__ void cp16(uint32_t smem_dst, const void* gsrc) {
    asm volatile("cp.async.cg.shared.global [%0], [%1], 16;" :: "r"(smem_dst), "l"(gsrc));
}
#define CP_COMMIT() asm volatile("cp.async.commit_group;")

__device__ __forceinline__ uint32_t su32(const void* p) {
    return (uint32_t)__cvta_generic_to_shared(p);
}

// A-tile SW128 packing: two 64B m-rows per 128B line, seg XOR (line&7).
__device__ __forceinline__ uint32_t swzA(int r, int c) {
    uint32_t seg = (uint32_t)(((r & 1) << 2) | (c >> 2));
    return (uint32_t)((r >> 1) * 128) + ((seg ^ ((r >> 1) & 7)) << 4) + ((c & 3) << 2);
}

// ldmatrix x4 (b16 form carrying tf32): matrices 0..3 = a0..a3 of m16n8k8 frag.
__device__ __forceinline__ void ldsm_x4(unsigned* a, uint32_t addr) {
    asm volatile("ldmatrix.sync.aligned.m8n8.x4.shared.b16 {%0,%1,%2,%3}, [%4];"
                 : "=r"(a[0]), "=r"(a[1]), "=r"(a[2]), "=r"(a[3])
                 : "r"(addr));
}

// ---------------- small fp32 GEMM: OUT[gr] = tf32(IN @ W[gr]) row-major ----------------
// Row tile 32 -> grid (128, 6) for occupancy.
template <int NOUT>
__global__ void __launch_bounds__(256) small_gemm(const float* __restrict__ IN,
                                                  const float* __restrict__ W,
                                                  float* __restrict__ OUT) {
    __shared__ float Xs[32][65];
    __shared__ float Ws[64][NOUT + 1];
    const int tid  = threadIdx.x;
    const int row0 = blockIdx.x * 32;
    const int gr   = blockIdx.y;

#pragma unroll
    for (int it = 0; it < 8; ++it) {
        int idx = tid + it * 256;
        Xs[idx >> 6][idx & 63] = IN[(size_t)(row0 + (idx >> 6)) * 64 + (idx & 63)];
    }
    const float* Wg = W + (size_t)gr * 64 * NOUT;
#pragma unroll
    for (int it = 0; it < (64 * NOUT) / 256; ++it) {
        int idx = tid + it * 256;
        Ws[idx / NOUT][idx % NOUT] = Wg[idx];
    }
    __syncthreads();

    constexpr int TX  = NOUT / 4;     // 16 or 8
    constexpr int TY  = 256 / TX;     // 16 or 32
    constexpr int RPT = 32 / TY;      // 2 or 1
    const int tx = tid % TX, ty = tid / TX;
    const int c0 = tx * 4, r0 = ty * RPT;

    float acc[RPT][4];
#pragma unroll
    for (int i = 0; i < RPT; ++i)
#pragma unroll
        for (int j = 0; j < 4; ++j) acc[i][j] = 0.f;

#pragma unroll
    for (int k = 0; k < 64; ++k) {
        float bb[4];
#pragma unroll
        for (int j = 0; j < 4; ++j) bb[j] = Ws[k][c0 + j];
#pragma unroll
        for (int i = 0; i < RPT; ++i) {
            float av = Xs[r0 + i][k];
#pragma unroll
            for (int j = 0; j < 4; ++j) acc[i][j] = fmaf(av, bb[j], acc[i][j]);
        }
    }
    float* Og = OUT + ((size_t)gr * NN + row0) * NOUT;
#pragma unroll
    for (int i = 0; i < RPT; ++i)
#pragma unroll
        for (int j = 0; j < 4; ++j)
            Og[(size_t)(r0 + i) * NOUT + c0 + j] = __uint_as_float(f2tf(acc[i][j]));
}

// ---------------- combine + layer-2 projection (row-major, row tile 32) ----------------
__global__ void __launch_bounds__(256) combine_gemm(const float* __restrict__ H,
                                                    const float* __restrict__ a,
                                                    const float* __restrict__ W,
                                                    float* __restrict__ OUT) {
    constexpr int NOUT = NCLS;
    __shared__ float Xs[32][65];
    __shared__ float Ws[64][NOUT + 1];
    const int tid  = threadIdx.x;
    const int row0 = blockIdx.x * 32;
    const int gr   = blockIdx.y;
    const float a0 = a[0], a1v = a[1], a2v = a[2];

    const size_t gstride = (size_t)NN * NHID;
#pragma unroll
    for (int it = 0; it < 8; ++it) {
        int idx = tid + it * 256;
        int r = idx >> 6, c = idx & 63;
        size_t off = (size_t)(row0 + r) * NHID + c;
        Xs[r][c] = a0 * H[off] + a1v * H[off + gstride] + a2v * H[off + 2 * gstride];
    }
    const float* Wg = W + (size_t)gr * 64 * NOUT;
#pragma unroll
    for (int it = 0; it < (64 * NOUT) / 256; ++it) {
        int idx = tid + it * 256;
        Ws[idx / NOUT][idx % NOUT] = Wg[idx];
    }
    __syncthreads();

    constexpr int TX  = NOUT / 4;   // 8
    constexpr int TY  = 256 / TX;   // 32
    constexpr int RPT = 32 / TY;    // 1
    const int tx = tid % TX, ty = tid / TX;
    const int c0 = tx * 4, r0 = ty * RPT;

    float acc[RPT][4];
#pragma unroll
    for (int i = 0; i < RPT; ++i)
#pragma unroll
        for (int j = 0; j < 4; ++j) acc[i][j] = 0.f;

#pragma unroll
    for (int k = 0; k < 64; ++k) {
        float bb[4];
#pragma unroll
        for (int j = 0; j < 4; ++j) bb[j] = Ws[k][c0 + j];
#pragma unroll
        for (int i = 0; i < RPT; ++i) {
            float av = Xs[r0 + i][k];
#pragma unroll
            for (int j = 0; j < 4; ++j) acc[i][j] = fmaf(av, bb[j], acc[i][j]);
        }
    }
    float* Og = OUT + ((size_t)gr * NN + row0) * NOUT;
#pragma unroll
    for (int i = 0; i < RPT; ++i)
#pragma unroll
        for (int j = 0; j < 4; ++j)
            Og[(size_t)(r0 + i) * NOUT + c0 + j] = __uint_as_float(f2tf(acc[i][j]));
}

// ---------------- big GEMM: FROZEN R10/R15 inner loop (ldmatrix A, preload, KB=16) ----------------
template <int NOUT>
__global__ void __launch_bounds__(256) big_gemm8(const float* __restrict__ adj,
                                                 const float* __restrict__ S,
                                                 float* __restrict__ Hp) {
    constexpr int TM   = 128;
    constexpr int KB   = 16;
    constexpr int ST   = 4;
    constexpr int ASZB = TM * 64;                     // 8192 bytes per A stage
    constexpr int BPAD = NOUT + 8;
    constexpr int BSZB = KB * BPAD * 4;               // bytes per B stage
    constexpr int WN   = (NOUT == 64) ? 32 : 16;
    constexpr int NJ   = WN / 8;                      // 4 or 2
    constexpr int MI   = 2;                           // WM = 32
    constexpr int SEGS = NOUT / 4;
    constexpr int BTOT = KB * SEGS;                   // B 16B-segs per chunk

    extern __shared__ char dyn[];
    char* Abuf = dyn;
    char* Bbuf = dyn + ST * ASZB;

    const int g    = blockIdx.y;
    const int zi   = blockIdx.z;                      // role*KSPL + ks
    const int role = zi / KSPL;
    const int ks   = zi % KSPL;
    const int row0 = blockIdx.x * TM;
    const int tid  = threadIdx.x;
    const int warp = tid >> 5, lane = tid & 31;
    const int gid  = lane >> 2, tg = lane & 3;
    const int wm   = warp >> 1, wn = warp & 1;        // 4x2 warp grid
    const int wrow = wm * 32, wcol = wn * WN;

    // ldmatrix lane mapping: matrices 0..3 = (a0,a1,a2,a3)
    const int lrow = (lane & 7) + (lane & 8);
    const int lsel = (lane >> 2) & 4;

    // uneven K split over 256 chunks: {86, 85, 85}
    const int c0   = (ks == 0) ? 0 : (86 + 85 * (ks - 1));
    const int cend = (ks == 0) ? 86 : (c0 + 85);

    float acc[MI][NJ][4];
#pragma unroll
    for (int i = 0; i < MI; ++i)
#pragma unroll
        for (int j = 0; j < NJ; ++j)
#pragma unroll
            for (int q = 0; q < 4; ++q) acc[i][j][q] = 0.f;

    const float* Ag = adj + ((size_t)(g * NR + role) * NN + row0) * NN;
    const float* Sg = S + (size_t)(g * NR + role) * NN * NOUT;

    const uint32_t sA = su32(Abuf);
    const uint32_t sB = su32(Bbuf);

    auto load_chunk = [&](int c, int st) {
        const uint32_t As = sA + st * ASZB;
        const uint32_t Bs = sB + st * BSZB;
#pragma unroll
        for (int it = 0; it < 2; ++it) {
            int cid = tid + it * 256;
            int r = cid >> 2, s4 = cid & 3;
            uint32_t seg = (uint32_t)(((r & 1) << 2) | s4);
            uint32_t dst = (uint32_t)((r >> 1) * 128) + ((seg ^ ((r >> 1) & 7)) << 4);
            cp16(As + dst, Ag + (size_t)r * NN + c * KB + s4 * 4);
        }
#pragma unroll
        for (int it = 0; it < (BTOT + 255) / 256; ++it) {
            int cid = tid + it * 256;
            if (cid < BTOT) {
                int r = cid / SEGS, sg = cid % SEGS;
                cp16(Bs + r * (BPAD * 4) + sg * 16, Sg + (size_t)(c * KB + r) * NOUT + sg * 4);
            }
        }
    };

    // prologue: lookahead 2
    load_chunk(c0, 0); CP_COMMIT();
    load_chunk(c0 + 1, 1); CP_COMMIT();

    for (int i = c0, li = 0; i < cend; ++i, ++li) {
        const int j = i + 2;
        if (j < cend) load_chunk(j, (li + 2) & (ST - 1));
        CP_COMMIT();                                  // possibly empty group
        asm volatile("cp.async.wait_group 2;");       // chunk i resident
        __syncthreads();                              // single barrier per chunk

        const uint32_t AsU = sA + (li & (ST - 1)) * ASZB;
        const float* Bs = (const float*)(Bbuf + (li & (ST - 1)) * BSZB);

        unsigned afr[2][MI][4];
        unsigned bfr[2][NJ][2];
#pragma unroll
        for (int kk = 0; kk < 2; ++kk) {
            const int k0 = kk * 8;
#pragma unroll
            for (int i2 = 0; i2 < MI; ++i2)
                ldsm_x4(afr[kk][i2], AsU + swzA(wrow + i2 * 16 + lrow, k0 + lsel));
#pragma unroll
            for (int j2 = 0; j2 < NJ; ++j2) {
                const int cb = wcol + j2 * 8 + gid;
                bfr[kk][j2][0] = __float_as_uint(Bs[(k0 + tg) * BPAD + cb]);
                bfr[kk][j2][1] = __float_as_uint(Bs[(k0 + tg + 4) * BPAD + cb]);
            }
        }
#pragma unroll
        for (int kk = 0; kk < 2; ++kk)
#pragma unroll
            for (int i2 = 0; i2 < MI; ++i2)
#pragma unroll
                for (int j2 = 0; j2 < NJ; ++j2)
                    mma_tf32(acc[i2][j2], afr[kk][i2], bfr[kk][j2]);
    }

    float* Hg = Hp + ((size_t)(g * NPART + zi) * NN + row0) * NOUT;
#pragma unroll
    for (int i2 = 0; i2 < MI; ++i2) {
#pragma unroll
        for (int j2 = 0; j2 < NJ; ++j2) {
            const int r0 = wrow + i2 * 16 + gid;
            const int cc = wcol + j2 * 8 + tg * 2;
            *(float2*)&Hg[(size_t)r0 * NOUT + cc]       = make_float2(acc[i2][j2][0], acc[i2][j2][1]);
            *(float2*)&Hg[(size_t)(r0 + 8) * NOUT + cc] = make_float2(acc[i2][j2][2], acc[i2][j2][3]);
        }
    }
}

// ---------------- fuse + attention (+ optional fused final combine), grid (FB, 3) ----------------
template <int NOUT, bool DO_COMBINE>
__global__ void __launch_bounds__(256) fuse_attn(const float* __restrict__ Hp,
                                                 const float* __restrict__ bias,
                                                 const float* __restrict__ Wk,
                                                 const float* __restrict__ Wq,
                                                 int layer, float inv_cnt,
                                                 float* __restrict__ H,
                                                 float* __restrict__ parts,
                                                 float* __restrict__ a_out,
                                                 int* __restrict__ cnt,
                                                 float* __restrict__ out,
                                                 int* __restrict__ flag,
                                                 int* __restrict__ done) {
    constexpr int Q4G = NN * NOUT / 4;
    constexpr int EPT = Q4G / (FB * 256);            // 2 (NOUT=64) or 1 (NOUT=32)
    constexpr int CG  = NOUT / 4;
    const int g   = blockIdx.y;
    const int tid = threadIdx.x;

    const float4* base = (const float4*)(Hp + (size_t)g * NPART * NN * NOUT);
    float4* Hg = (float4*)(H + (size_t)g * NN * NOUT);
    const float4* bv = (const float4*)(bias + g * NOUT);

    float lsum = 0.f;
#pragma unroll
    for (int it = 0; it < EPT; ++it) {
        int idx = blockIdx.x * 256 + tid + it * (FB * 256);
        float4 acc = base[idx];
#pragma unroll
        for (int p = 1; p < NPART; ++p) {
            float4 v = base[(size_t)p * Q4G + idx];
            acc.x += v.x; acc.y += v.y; acc.z += v.z; acc.w += v.w;
        }
        float4 bb = bv[idx % CG];
        float4 r;
        r.x = fmaxf(CORR * acc.x + bb.x, 0.f);
        r.y = fmaxf(CORR * acc.y + bb.y, 0.f);
        r.z = fmaxf(CORR * acc.z + bb.z, 0.f);
        r.w = fmaxf(CORR * acc.w + bb.w, 0.f);
        Hg[idx] = r;
        lsum += r.x + r.y + r.z + r.w;
    }
#pragma unroll
    for (int off = 16; off; off >>= 1) lsum += __shfl_xor_sync(0xffffffffu, lsum, off);
    __shared__ float wsum[8];
    if ((tid & 31) == 0) wsum[tid >> 5] = lsum;
    __syncthreads();
    if (tid == 0) {
        float s = 0.f;
#pragma unroll
        for (int w = 0; w < 8; ++w) s += wsum[w];
        parts[g * FB + blockIdx.x] = s;
    }

    __threadfence();
    __shared__ int lastb;
    if (tid == 0) lastb = (atomicAdd(cnt, 1) == FB * NG - 1) ? 1 : 0;
    __syncthreads();

    if (lastb) {
        __shared__ float ssq[NG];
        if (tid < NG) {
            float s = 0.f;
            for (int i = 0; i < FB; ++i) s += parts[tid * FB + i];   // fixed order
            ssq[tid] = s * inv_cnt;
        }
        __syncthreads();
        if (tid == 0) {
            const float* wk = Wk + layer * 9;
            const float* wq = Wq + layer * 9;
            float kk[NG], lg[NG];
#pragma unroll
            for (int j = 0; j < NG; ++j)
                kk[j] = fmaxf(ssq[0] * wk[j] + ssq[1] * wk[3 + j] + ssq[2] * wk[6 + j], 0.f);
            float m = -1e30f;
#pragma unroll
            for (int j = 0; j < NG; ++j) {
                lg[j] = kk[0] * wq[j] + kk[1] * wq[3 + j] + kk[2] * wq[6 + j];
                m = fmaxf(m, lg[j]);
            }
            float e0 = expf(lg[0] - m), e1 = expf(lg[1] - m), e2 = expf(lg[2] - m);
            float inv = 1.f / (e0 + e1 + e2);
            a_out[0] = e0 * inv;
            a_out[1] = e1 * inv;
            a_out[2] = e2 * inv;
            *cnt = 0;   // reset for replay
            if (DO_COMBINE) {
                __threadfence();
                atomicExch(flag, 1);    // publish a_out + all H
            }
        }
    }

    if (DO_COMBINE) {
        if (g != 0) return;             // only gene-0 CTAs combine (all co-resident)
        if (tid == 0) {
            while (atomicAdd(flag, 0) == 0) {}
        }
        __syncthreads();
        const float a0 = __ldcg(&a_out[0]);
        const float a1 = __ldcg(&a_out[1]);
        const float a2 = __ldcg(&a_out[2]);
        constexpr int Q = NN * NOUT / 4;
        constexpr int PER = Q / FB;
        const float4* h4 = (const float4*)H;
        float4* o4 = (float4*)out;
#pragma unroll
        for (int it = 0; it < PER / 256; ++it) {
            int idx = blockIdx.x * PER + tid + it * 256;
            float4 x0 = __ldcg(&h4[idx]);
            float4 x1 = __ldcg(&h4[idx + Q]);
            float4 x2 = __ldcg(&h4[idx + 2 * Q]);
            float4 r;
            r.x = a0 * x0.x + a1 * x1.x + a2 * x2.x;
            r.y = a0 * x0.y + a1 * x1.y + a2 * x2.y;
            r.z = a0 * x0.z + a1 * x1.z + a2 * x2.z;
            r.w = a0 * x0.w + a1 * x1.w + a2 * x2.w;
            o4[idx] = r;
        }
        __threadfence();
        if (tid == 0) {
            if (atomicAdd(done, 1) == FB - 1) {
                atomicExch(done, 0);
                atomicExch(flag, 0);
            }
        }
    }
}

// ---------------- launch ----------------
extern "C" void kernel_launch(void* const* d_in, const int* in_sizes, int n_in,
                              void* d_out, int out_size) {
    const float* x   = (const float*)d_in[0];
    const float* adj = (const float*)d_in[1];
    const float* W1  = (const float*)d_in[2];
    const float* b1  = (const float*)d_in[3];
    const float* W2  = (const float*)d_in[4];
    const float* b2  = (const float*)d_in[5];
    const float* Wk  = (const float*)d_in[6];
    const float* Wq  = (const float*)d_in[7];
    float* out = (float*)d_out;

    float *s1, *hp1, *h1, *s2, *hp2, *h2, *p1, *p2, *a1, *a2;
    int *c1, *c2, *fl2, *dn2;
    cudaGetSymbolAddress((void**)&s1, g_s1);
    cudaGetSymbolAddress((void**)&hp1, g_hp1);
    cudaGetSymbolAddress((void**)&h1, g_h1);
    cudaGetSymbolAddress((void**)&s2, g_s2);
    cudaGetSymbolAddress((void**)&hp2, g_hp2);
    cudaGetSymbolAddress((void**)&h2, g_h2);
    cudaGetSymbolAddress((void**)&p1, g_p1);
    cudaGetSymbolAddress((void**)&p2, g_p2);
    cudaGetSymbolAddress((void**)&a1, g_a1);
    cudaGetSymbolAddress((void**)&a2, g_a2);
    cudaGetSymbolAddress((void**)&c1, g_cnt1);
    cudaGetSymbolAddress((void**)&c2, g_cnt2);
    cudaGetSymbolAddress((void**)&fl2, g_flag2);
    cudaGetSymbolAddress((void**)&dn2, g_done2);

    constexpr int SM64 = 4 * (128 * 64 + 16 * (NHID + 8) * 4);   // 51200 B
    constexpr int SM32 = 4 * (128 * 64 + 16 * (NCLS + 8) * 4);   // 43008 B
    cudaFuncSetAttribute(big_gemm8<NHID>, cudaFuncAttributeMaxDynamicSharedMemorySize, SM64);
    cudaFuncSetAttribute(big_gemm8<NCLS>, cudaFuncAttributeMaxDynamicSharedMemorySize, SM32);

    // Layer 1
    small_gemm<NHID><<<dim3(NN / 32, NG * NR), 256>>>(x, W1, s1);
    big_gemm8<NHID><<<dim3(NN / 128, NG, NPART), 256, SM64>>>(adj, s1, hp1);
    fuse_attn<NHID, false><<<dim3(FB, NG), 256>>>(hp1, b1, Wk, Wq, 0,
                                                  1.f / ((float)NN * NHID),
                                                  h1, p1, a1, c1,
                                                  nullptr, nullptr, nullptr);
    // Layer 2 (combine fused into projection; final combine fused into fuse_attn)
    combine_gemm<<<dim3(NN / 32, NG * NR), 256>>>(h1, a1, W2, s2);
    big_gemm8<NCLS><<<dim3(NN / 128, NG, NPART), 256, SM32>>>(adj, s2, hp2);
    fuse_attn<NCLS, true><<<dim3(FB, NG), 256>>>(hp2, b2, Wk, Wq, 1,
                                                 1.f / ((float)NN * NCLS),
                                                 h2, p2, a2, c2,
                                                 out, fl2, dn2);
}